// round 5
// baseline (speedup 1.0000x reference)
#include <cuda_runtime.h>
#include <math.h>

// Problem constants (B=2, S=2048, D=1024, H=16, Dk=64)
#define BB 2
#define SS 2048
#define DD 1024
#define HH 16
#define DK 64
#define BH (BB*HH)

#define QSCALE (0.125f * 1.44269504088896340736f)

typedef unsigned long long u64;

__device__ __forceinline__ u64 pack_dup(float x) {
    u64 r; asm("mov.b64 %0, {%1,%1};" : "=l"(r) : "f"(x)); return r;
}
__device__ __forceinline__ void fma2(u64& d, u64 a, u64 b) {
    asm("fma.rn.f32x2 %0, %1, %2, %0;" : "+l"(d) : "l"(a), "l"(b));
}
__device__ __forceinline__ float2 unpk(u64 v) {
    float2 f; asm("mov.b64 {%0,%1}, %2;" : "=f"(f.x), "=f"(f.y) : "l"(v)); return f;
}

// ---- static device scratch ----
__device__ float g_Qh[BH*SS*DK];
__device__ float g_Kh[BH*SS*DK];
__device__ float g_lb[BH*SS];
__device__ float g_w [BH*SS];
__device__ float g_ypart[16*BB*HH*DD];
__device__ float g_y [BB*HH*DD];
__device__ float g_cs[BB*DD];
__device__ float g_csp[64*DD];
__device__ float g_outp[64*DD];
__device__ int   g_qidx[BB*SS];
__device__ int   g_cnt [BB];
__device__ float g_cntf[BB];

// ---------------------------------------------------------------------------
// Kernel 0: deterministic mask compaction
// ---------------------------------------------------------------------------
__global__ void k_compact(const int* __restrict__ mask) {
    int b = blockIdx.x;
    int tid = threadIdx.x;
    __shared__ int cnts[256];
    __shared__ int offs[256];
    int base = tid * 8;
    int loc[8];
    int c = 0;
#pragma unroll
    for (int i = 0; i < 8; i++) { loc[i] = mask[b*SS + base + i]; c += (loc[i] != 0); }
    cnts[tid] = c;
    __syncthreads();
    if (tid == 0) {
        int run = 0;
        for (int i = 0; i < 256; i++) { offs[i] = run; run += cnts[i]; }
        g_cnt[b] = run;
        g_cntf[b] = (float)run;
    }
    __syncthreads();
    int o = offs[tid];
#pragma unroll
    for (int i = 0; i < 8; i++) {
        if (loc[i] != 0) { g_qidx[b*SS + o] = base + i; o++; }
    }
}

// ---------------------------------------------------------------------------
// Kernel 1: projection GEMM, 128m x 256n tile, 8x16 per thread, f32x2 FFMA.
// ---------------------------------------------------------------------------
__global__ __launch_bounds__(256) void k_proj(
    const float* __restrict__ X, const float* __restrict__ W,
    const float* __restrict__ bias, float scale, int which)
{
    __shared__ __align__(16) float As[16][128];   // [k][m]
    __shared__ __align__(16) float Bs[16][256];   // [k][n]
    float* Out = which ? g_Kh : g_Qh;

    int tid = threadIdx.x;
    int tx = tid & 15, ty = tid >> 4;
    int m0 = blockIdx.x * 128;
    int n0 = blockIdx.y * 256;

    u64 acc2[8][8];
#pragma unroll
    for (int i = 0; i < 8; i++)
#pragma unroll
        for (int j = 0; j < 8; j++) acc2[i][j] = 0ull;

    for (int k0 = 0; k0 < 1024; k0 += 16) {
#pragma unroll
        for (int i = 0; i < 2; i++) {
            int idx = tid * 2 + i;           // 0..511 float4s
            int r   = idx >> 2;
            int kq  = idx & 3;
            float4 va = *(const float4*)(X + (size_t)(m0 + r) * 1024 + k0 + kq * 4);
            As[kq*4+0][r] = va.x; As[kq*4+1][r] = va.y;
            As[kq*4+2][r] = va.z; As[kq*4+3][r] = va.w;
        }
#pragma unroll
        for (int i = 0; i < 4; i++) {
            int idx = tid + 256 * i;         // 0..1023 float4s
            int kr = idx >> 6;               // 0..15
            int c4 = idx & 63;
            *(float4*)(&Bs[kr][c4*4]) =
                *(const float4*)(W + (size_t)(k0 + kr) * 1024 + n0 + c4 * 4);
        }
        __syncthreads();
#pragma unroll
        for (int kk = 0; kk < 16; kk++) {
            float4 a0 = *(const float4*)(&As[kk][ty*8]);
            float4 a1 = *(const float4*)(&As[kk][ty*8+4]);
            const ulonglong2* bp = (const ulonglong2*)(&Bs[kk][tx*16]);
            ulonglong2 q0 = bp[0], q1 = bp[1], q2 = bp[2], q3 = bp[3];
            u64 bb[8] = {q0.x,q0.y,q1.x,q1.y,q2.x,q2.y,q3.x,q3.y};
            float a[8] = {a0.x,a0.y,a0.z,a0.w,a1.x,a1.y,a1.z,a1.w};
            u64 aa[8];
#pragma unroll
            for (int i = 0; i < 8; i++) aa[i] = pack_dup(a[i]);
#pragma unroll
            for (int i = 0; i < 8; i++)
#pragma unroll
                for (int j = 0; j < 8; j++) fma2(acc2[i][j], aa[i], bb[j]);
        }
        __syncthreads();
    }
#pragma unroll
    for (int i = 0; i < 8; i++) {
        int row = m0 + ty*8 + i;
        int b = row >> 11, s = row & 2047;
#pragma unroll
        for (int j = 0; j < 8; j++) {
            float2 p = unpk(acc2[i][j]);
            int col = n0 + tx*16 + j*2;
            int h0 = col >> 6, dd0 = col & 63;
            int h1 = (col+1) >> 6, dd1 = (col+1) & 63;
            Out[(((size_t)(b*HH + h0) * SS + s) << 6) + dd0] =
                (p.x + bias[col]) * scale;
            Out[(((size_t)(b*HH + h1) * SS + s) << 6) + dd1] =
                (p.y + bias[col+1]) * scale;
        }
    }
}

// ---------------------------------------------------------------------------
// Kernel 2 (pass A): 128q x 256k tiles, 8x16 per thread, f32x2.
// dyn smem floats: Qs[64*128]@0 | Ks[64*256]@8192 | red[128*16]@24576  (106496 B)
// ---------------------------------------------------------------------------
__global__ __launch_bounds__(256) void k_lsum() {
    extern __shared__ __align__(16) float sm[];
    float* Qs  = sm;              // [d][q] 64x128
    float* Ks  = sm + 8192;       // [d][k] 64x256
    float* red = sm + 24576;      // [q][16]

    int qt = blockIdx.x;          // 0..15
    int bh = blockIdx.y;          // 0..31
    int b  = bh >> 4;
    int cnt = g_cnt[b];
    if (qt * 128 >= cnt) return;

    int tid = threadIdx.x;
    int tx = tid & 15, ty = tid >> 4;
    const float* Qbase = g_Qh + (size_t)bh * SS * 64;
    const float* Kbase = g_Kh + (size_t)bh * SS * 64;

    // gather 128 compacted Q rows into Qs[d][q]
#pragma unroll
    for (int i = 0; i < 8; i++) {
        int idx = tid + 256 * i;       // 0..2047 float4s
        int qq = idx >> 4, d4 = idx & 15;
        int ci = qt * 128 + qq;
        float4 vq = make_float4(0.f, 0.f, 0.f, 0.f);
        if (ci < cnt) {
            int s = g_qidx[b*SS + ci];
            vq = *(const float4*)(Qbase + ((size_t)s << 6) + d4 * 4);
        }
        Qs[(d4*4+0)*128 + qq] = vq.x; Qs[(d4*4+1)*128 + qq] = vq.y;
        Qs[(d4*4+2)*128 + qq] = vq.z; Qs[(d4*4+3)*128 + qq] = vq.w;
    }

    float rsum[8];
#pragma unroll
    for (int i = 0; i < 8; i++) rsum[i] = 0.f;

    for (int kt = 0; kt < 8; kt++) {          // 8 tiles of 256 keys
#pragma unroll
        for (int i = 0; i < 16; i++) {
            int idx = tid + 256 * i;          // 0..4095 float4s
            int r = idx >> 4, d4 = idx & 15;
            float4 vk = *(const float4*)(Kbase + ((size_t)(kt*256 + r) << 6) + d4 * 4);
            Ks[(d4*4+0)*256 + r] = vk.x; Ks[(d4*4+1)*256 + r] = vk.y;
            Ks[(d4*4+2)*256 + r] = vk.z; Ks[(d4*4+3)*256 + r] = vk.w;
        }
        __syncthreads();
        u64 acc2[8][8];
#pragma unroll
        for (int i = 0; i < 8; i++)
#pragma unroll
            for (int j = 0; j < 8; j++) acc2[i][j] = 0ull;
#pragma unroll 4
        for (int d = 0; d < 64; d++) {
            float4 a0 = *(const float4*)(Qs + d*128 + ty*8);
            float4 a1 = *(const float4*)(Qs + d*128 + ty*8 + 4);
            const ulonglong2* bp = (const ulonglong2*)(Ks + d*256 + tx*16);
            ulonglong2 q0 = bp[0], q1 = bp[1], q2 = bp[2], q3 = bp[3];
            u64 bb[8] = {q0.x,q0.y,q1.x,q1.y,q2.x,q2.y,q3.x,q3.y};
            float a[8] = {a0.x,a0.y,a0.z,a0.w,a1.x,a1.y,a1.z,a1.w};
            u64 aa[8];
#pragma unroll
            for (int i = 0; i < 8; i++) aa[i] = pack_dup(a[i]);
#pragma unroll
            for (int i = 0; i < 8; i++)
#pragma unroll
                for (int j = 0; j < 8; j++) fma2(acc2[i][j], aa[i], bb[j]);
        }
#pragma unroll
        for (int i = 0; i < 8; i++)
#pragma unroll
            for (int j = 0; j < 8; j++) {
                float2 e = unpk(acc2[i][j]);
                rsum[i] += exp2f(e.x) + exp2f(e.y);
            }
        __syncthreads();
    }
#pragma unroll
    for (int i = 0; i < 8; i++) red[(ty*8 + i)*16 + tx] = rsum[i];
    __syncthreads();
    if (tid < 128) {
        float l = 0.f;
#pragma unroll
        for (int t = 0; t < 16; t++) l += red[tid*16 + t];
        int ci = qt * 128 + tid;
        if (ci < cnt) g_lb[bh*SS + ci] = log2f(l);
    }
}

// ---------------------------------------------------------------------------
// Kernel 3 (pass B): 256-key tiles, iterate compact q in 128-row tiles; f32x2.
// dyn smem floats: Ks[64*256]@0 | Qs[64*128]@16384 | red[256*16]@24576 | lbs[128]@28672
// (115200 B)
// ---------------------------------------------------------------------------
__global__ __launch_bounds__(256) void k_wsum() {
    extern __shared__ __align__(16) float sm[];
    float* Ks  = sm;              // [d][k] 64x256
    float* Qs  = sm + 16384;      // [d][q] 64x128
    float* red = sm + 24576;      // [k][16]
    float* lbs = sm + 28672;

    int kt = blockIdx.x;          // 0..7
    int bh = blockIdx.y;
    int b  = bh >> 4;
    int cnt = g_cnt[b];

    int tid = threadIdx.x;
    int tx = tid & 15, ty = tid >> 4;
    const float* Qbase = g_Qh + (size_t)bh * SS * 64;
    const float* Kbase = g_Kh + (size_t)bh * SS * 64;

#pragma unroll
    for (int i = 0; i < 16; i++) {
        int idx = tid + 256 * i;
        int r = idx >> 4, d4 = idx & 15;
        float4 vk = *(const float4*)(Kbase + ((size_t)(kt*256 + r) << 6) + d4 * 4);
        Ks[(d4*4+0)*256 + r] = vk.x; Ks[(d4*4+1)*256 + r] = vk.y;
        Ks[(d4*4+2)*256 + r] = vk.z; Ks[(d4*4+3)*256 + r] = vk.w;
    }

    float wacc[16];
#pragma unroll
    for (int j = 0; j < 16; j++) wacc[j] = 0.f;

    int nqt = (cnt + 127) >> 7;
    for (int qt = 0; qt < nqt; qt++) {
        __syncthreads();   // protect Qs/lbs from previous iteration's readers
#pragma unroll
        for (int i = 0; i < 8; i++) {
            int idx = tid + 256 * i;
            int qq = idx >> 4, d4 = idx & 15;
            int ci = qt * 128 + qq;
            float4 vq = make_float4(0.f, 0.f, 0.f, 0.f);
            if (ci < cnt) {
                int s = g_qidx[b*SS + ci];
                vq = *(const float4*)(Qbase + ((size_t)s << 6) + d4 * 4);
            }
            Qs[(d4*4+0)*128 + qq] = vq.x; Qs[(d4*4+1)*128 + qq] = vq.y;
            Qs[(d4*4+2)*128 + qq] = vq.z; Qs[(d4*4+3)*128 + qq] = vq.w;
        }
        if (tid < 128) {
            int ci = qt * 128 + tid;
            lbs[tid] = (ci < cnt) ? g_lb[bh*SS + ci] : 1e9f;
        }
        __syncthreads();
        u64 acc2[8][8];
#pragma unroll
        for (int i = 0; i < 8; i++)
#pragma unroll
            for (int j = 0; j < 8; j++) acc2[i][j] = 0ull;
#pragma unroll 4
        for (int d = 0; d < 64; d++) {
            float4 a0 = *(const float4*)(Qs + d*128 + ty*8);
            float4 a1 = *(const float4*)(Qs + d*128 + ty*8 + 4);
            const ulonglong2* bp = (const ulonglong2*)(Ks + d*256 + tx*16);
            ulonglong2 q0 = bp[0], q1 = bp[1], q2 = bp[2], q3 = bp[3];
            u64 bb[8] = {q0.x,q0.y,q1.x,q1.y,q2.x,q2.y,q3.x,q3.y};
            float a[8] = {a0.x,a0.y,a0.z,a0.w,a1.x,a1.y,a1.z,a1.w};
            u64 aa[8];
#pragma unroll
            for (int i = 0; i < 8; i++) aa[i] = pack_dup(a[i]);
#pragma unroll
            for (int i = 0; i < 8; i++)
#pragma unroll
                for (int j = 0; j < 8; j++) fma2(acc2[i][j], aa[i], bb[j]);
        }
#pragma unroll
        for (int i = 0; i < 8; i++) {
            float lb = lbs[ty*8 + i];
#pragma unroll
            for (int j = 0; j < 8; j++) {
                float2 e = unpk(acc2[i][j]);
                wacc[2*j]   += exp2f(e.x - lb);
                wacc[2*j+1] += exp2f(e.y - lb);
            }
        }
    }
    __syncthreads();
#pragma unroll
    for (int j = 0; j < 16; j++) red[(tx*16 + j)*16 + ty] = wacc[j];
    __syncthreads();
    {
        float w = 0.f;
#pragma unroll
        for (int t = 0; t < 16; t++) w += red[tid*16 + t];
        g_w[bh*SS + kt*256 + tid] = w;
    }
}

// ---------------------------------------------------------------------------
// Kernel 4: y[b,h,j] = sum_k w[b,h,k] * v[b,k,j]
// ---------------------------------------------------------------------------
__global__ __launch_bounds__(256) void k_ypart(const float* __restrict__ v) {
    int id = blockIdx.x;
    int kt = id & 15;
    int jt = (id >> 4) & 3;
    int b  = id >> 6;
    __shared__ float wsh[16][128];
    int tid = threadIdx.x;
#pragma unroll
    for (int i = 0; i < 8; i++) {
        int idx = tid + 256 * i;
        int h = idx >> 7, kk = idx & 127;
        wsh[h][kk] = g_w[(b*HH + h) * SS + kt*128 + kk];
    }
    __syncthreads();
    int j = jt * 256 + tid;
    float acc[16];
#pragma unroll
    for (int h = 0; h < 16; h++) acc[h] = 0.f;
    const float* vb = v + ((size_t)b * SS + kt*128) * 1024 + j;
    for (int kk = 0; kk < 128; kk++) {
        float vv = vb[(size_t)kk * 1024];
#pragma unroll
        for (int h = 0; h < 16; h++) acc[h] += wsh[h][kk] * vv;
    }
#pragma unroll
    for (int h = 0; h < 16; h++)
        g_ypart[((size_t)(kt*BB + b) * HH + h) * DD + j] = acc[h];
}

__global__ void k_yred() {
    int i = blockIdx.x * 256 + threadIdx.x;
    float s = 0.f;
#pragma unroll
    for (int kt = 0; kt < 16; kt++) s += g_ypart[(size_t)kt * (BB*HH*DD) + i];
    g_y[i] = s;
}

// ---------------------------------------------------------------------------
// Kernel 5: cs[b,c] = sum_j y[b,h(c),j]*Wv[j,c] + cnt_b*bv[c]  (split-j)
// ---------------------------------------------------------------------------
__global__ void k_cs_part(const float* __restrict__ Wv) {
    int bid = blockIdx.x;          // 64 blocks: b = bid>>5, jc = bid&31
    int b = bid >> 5, jc = bid & 31;
    int tid = threadIdx.x;
    int c0 = tid * 4;
    int h = c0 >> 6;
    const float* yrow = g_y + (size_t)(b*HH + h) * DD;
    float4 s = make_float4(0.f, 0.f, 0.f, 0.f);
#pragma unroll 8
    for (int j = jc*32; j < jc*32 + 32; j++) {
        float yv = yrow[j];
        float4 w4 = *(const float4*)(Wv + (size_t)j * 1024 + c0);
        s.x += yv * w4.x; s.y += yv * w4.y; s.z += yv * w4.z; s.w += yv * w4.w;
    }
    *(float4*)(g_csp + (size_t)bid * DD + c0) = s;
}

__global__ void k_cs_red(const float* __restrict__ bv) {
    int idx = blockIdx.x * 256 + threadIdx.x;   // 0..2047
    int b = idx >> 10, c = idx & 1023;
    float s = 0.f;
#pragma unroll
    for (int jc = 0; jc < 32; jc++) s += g_csp[(size_t)(b*32 + jc) * DD + c];
    g_cs[idx] = s + g_cntf[b] * bv[c];
}

// ---------------------------------------------------------------------------
// Kernel 6: out[b,d] = sum_c cs[b,c]*Wo[c,d] + cnt_b*bo[d]   (split-c)
// ---------------------------------------------------------------------------
__global__ void k_out_part(const float* __restrict__ Wo) {
    int bid = blockIdx.x;
    int b = bid >> 5, jc = bid & 31;
    int tid = threadIdx.x;
    int d0 = tid * 4;
    const float* cs = g_cs + (size_t)b * 1024;
    float4 s = make_float4(0.f, 0.f, 0.f, 0.f);
#pragma unroll 8
    for (int c = jc*32; c < jc*32 + 32; c++) {
        float cv = cs[c];
        float4 w4 = *(const float4*)(Wo + (size_t)c * 1024 + d0);
        s.x += cv * w4.x; s.y += cv * w4.y; s.z += cv * w4.z; s.w += cv * w4.w;
    }
    *(float4*)(g_outp + (size_t)bid * DD + d0) = s;
}

__global__ void k_out_red(const float* __restrict__ bo, float* __restrict__ out) {
    int idx = blockIdx.x * 256 + threadIdx.x;   // 0..2047
    int b = idx >> 10, d = idx & 1023;
    float s = 0.f;
#pragma unroll
    for (int jc = 0; jc < 32; jc++) s += g_outp[(size_t)(b*32 + jc) * DD + d];
    out[idx] = s + g_cntf[b] * bo[d];
}

// ---------------------------------------------------------------------------
extern "C" void kernel_launch(void* const* d_in, const int* in_sizes, int n_in,
                              void* d_out, int out_size) {
    const float* q    = (const float*)d_in[0];
    const float* k    = (const float*)d_in[1];
    const float* v    = (const float*)d_in[2];
    const int*   mask = (const int*)  d_in[3];
    const float* Wq   = (const float*)d_in[4];
    const float* bq   = (const float*)d_in[5];
    const float* Wk   = (const float*)d_in[6];
    const float* bk   = (const float*)d_in[7];
    const float* Wv   = (const float*)d_in[8];
    const float* bv   = (const float*)d_in[9];
    const float* Wo   = (const float*)d_in[10];
    const float* bo   = (const float*)d_in[11];
    float* out = (float*)d_out;

    cudaFuncSetAttribute(k_lsum, cudaFuncAttributeMaxDynamicSharedMemorySize, 106496);
    cudaFuncSetAttribute(k_wsum, cudaFuncAttributeMaxDynamicSharedMemorySize, 115200);

    k_compact<<<BB, 256>>>(mask);
    k_proj<<<dim3(32, 4), 256>>>(q, Wq, bq, QSCALE, 0);
    k_proj<<<dim3(32, 4), 256>>>(k, Wk, bk, 1.0f, 1);
    k_lsum<<<dim3(16, 32), 256, 106496>>>();
    k_wsum<<<dim3(8, 32), 256, 115200>>>();
    k_ypart<<<128, 256>>>(v);
    k_yred<<<128, 256>>>();
    k_cs_part<<<64, 256>>>(Wv);
    k_cs_red<<<8, 256>>>(bv);
    k_out_part<<<64, 256>>>(Wo);
    k_out_red<<<8, 256>>>(bo, out);
}

// round 7
// speedup vs baseline: 3.6734x; 3.6734x over previous
#include <cuda_runtime.h>
#include <math.h>
#include <stdint.h>

// Problem constants (B=2, S=2048, D=1024, H=16, Dk=64)
#define BB 2
#define SS 2048
#define DD 1024
#define HH 16
#define DK 64
#define BH (BB*HH)

#define QSCALE (0.125f * 1.44269504088896340736f)
#define PAD 68   // smem row stride in words: bank-conflict-free for frag LDS

__device__ __forceinline__ uint32_t f2tf(float x) {
    uint32_t r; asm("cvt.rna.tf32.f32 %0, %1;" : "=r"(r) : "f"(x)); return r;
}
__device__ __forceinline__ void mma8(float* d, const uint32_t* a, uint32_t b0, uint32_t b1) {
    asm("mma.sync.aligned.m16n8k8.row.col.f32.tf32.tf32.f32 "
        "{%0,%1,%2,%3}, {%4,%5,%6,%7}, {%8,%9}, {%0,%1,%2,%3};"
        : "+f"(d[0]), "+f"(d[1]), "+f"(d[2]), "+f"(d[3])
        : "r"(a[0]), "r"(a[1]), "r"(a[2]), "r"(a[3]), "r"(b0), "r"(b1));
}

// ---- static device scratch ----
__device__ float g_Qh[BH*SS*DK];
__device__ float g_Kh[BH*SS*DK];
__device__ float g_lb[BH*SS];
__device__ float g_w [BH*SS];
__device__ float g_ypart[16*BB*HH*DD];
__device__ float g_y [BB*HH*DD];
__device__ float g_cs[BB*DD];
__device__ float g_csp[64*DD];
__device__ float g_outp[64*DD];
__device__ int   g_qidx[BB*SS];
__device__ int   g_cnt [BB];
__device__ float g_cntf[BB];

// ---------------------------------------------------------------------------
// Kernel 0: deterministic mask compaction
// ---------------------------------------------------------------------------
__global__ void k_compact(const int* __restrict__ mask) {
    int b = blockIdx.x;
    int tid = threadIdx.x;
    __shared__ int cnts[256];
    __shared__ int offs[256];
    int base = tid * 8;
    int loc[8];
    int c = 0;
#pragma unroll
    for (int i = 0; i < 8; i++) { loc[i] = mask[b*SS + base + i]; c += (loc[i] != 0); }
    cnts[tid] = c;
    __syncthreads();
    if (tid == 0) {
        int run = 0;
        for (int i = 0; i < 256; i++) { offs[i] = run; run += cnts[i]; }
        g_cnt[b] = run;
        g_cntf[b] = (float)run;
    }
    __syncthreads();
    int o = offs[tid];
#pragma unroll
    for (int i = 0; i < 8; i++) {
        if (loc[i] != 0) { g_qidx[b*SS + o] = base + i; o++; }
    }
}

// ---------------------------------------------------------------------------
// Kernel 1: projection GEMM via tf32 mma. Out = (X@W + bias)*scale, head-major.
// Block: 128m x 128n. Warp w -> rows [w*16, w*16+16). dyn smem 69632 B.
// ---------------------------------------------------------------------------
__global__ __launch_bounds__(256) void k_proj(
    const float* __restrict__ X, const float* __restrict__ W,
    const float* __restrict__ bias, float scale, int which)
{
    extern __shared__ __align__(16) uint32_t smu[];
    uint32_t* Xs = smu;            // [128 m][PAD]
    uint32_t* Ws = smu + 128*PAD;  // [128 n][PAD]  (W transposed: Ws[n][k])
    float* Out = which ? g_Kh : g_Qh;

    int tid = threadIdx.x;
    int w = tid >> 5, lane = tid & 31;
    int g = lane >> 2, t = lane & 3;
    int m0 = blockIdx.x * 128;
    int n0 = blockIdx.y * 128;

    float Dp[16][4];
#pragma unroll
    for (int nc = 0; nc < 16; nc++)
#pragma unroll
        for (int j = 0; j < 4; j++) Dp[nc][j] = 0.f;

    for (int k0 = 0; k0 < 1024; k0 += 64) {
        __syncthreads();
        // stage X tile 128m x 64k (coalesced float4 along k)
#pragma unroll
        for (int i = 0; i < 8; i++) {
            int idx = tid + 256 * i;            // 2048 float4
            int row = idx >> 4, k4 = idx & 15;
            float4 v = *(const float4*)(X + (size_t)(m0 + row) * 1024 + k0 + k4 * 4);
            uint4 u; u.x = f2tf(v.x); u.y = f2tf(v.y); u.z = f2tf(v.z); u.w = f2tf(v.w);
            *(uint4*)(Xs + row*PAD + k4*4) = u;
        }
        // stage W transposed: Ws[n][k] = W[k0+k][n0+n]; coalesced LDG.32 along n
#pragma unroll
        for (int i = 0; i < 8; i++) {
            int idx = tid + 256 * i;            // 2048: n(128) x k4(16)
            int n = idx & 127, k4 = idx >> 7;
            const float* wp = W + (size_t)(k0 + k4*4) * 1024 + n0 + n;
            uint4 u;
            u.x = f2tf(wp[0]);
            u.y = f2tf(wp[1024]);
            u.z = f2tf(wp[2048]);
            u.w = f2tf(wp[3072]);
            *(uint4*)(Ws + n*PAD + k4*4) = u;
        }
        __syncthreads();
        // A fragments for this k-tile (16 rows x 64 k)
        uint32_t A[8][4];
#pragma unroll
        for (int kc = 0; kc < 8; kc++) {
            int r0 = (w*16 + g)*PAD + t + 8*kc;
            A[kc][0] = Xs[r0];
            A[kc][1] = Xs[r0 + 8*PAD];
            A[kc][2] = Xs[r0 + 4];
            A[kc][3] = Xs[r0 + 8*PAD + 4];
        }
#pragma unroll
        for (int nc = 0; nc < 16; nc++) {
            int nb = (nc*8 + g)*PAD + t;
#pragma unroll
            for (int kc = 0; kc < 8; kc++)
                mma8(Dp[nc], A[kc], Ws[nb + 8*kc], Ws[nb + 8*kc + 4]);
        }
    }
    // epilogue: scatter to head-major [((b*H+h)*S+s)<<6)+dd]
    int row0 = m0 + w*16 + g;
#pragma unroll
    for (int nc = 0; nc < 16; nc++) {
        int col = n0 + nc*8 + 2*t;
        float bx = bias[col], by = bias[col+1];
        int h = col >> 6, dd = col & 63;
        {
            int b_ = row0 >> 11, s = row0 & 2047;
            float2 o = make_float2((Dp[nc][0] + bx) * scale, (Dp[nc][1] + by) * scale);
            *(float2*)(Out + (((size_t)(b_*HH + h) * SS + s) << 6) + dd) = o;
        }
        {
            int row1 = row0 + 8;
            int b_ = row1 >> 11, s = row1 & 2047;
            float2 o = make_float2((Dp[nc][2] + bx) * scale, (Dp[nc][3] + by) * scale);
            *(float2*)(Out + (((size_t)(b_*HH + h) * SS + s) << 6) + dd) = o;
        }
    }
}

// ---------------------------------------------------------------------------
// Kernel 2 (pass A): lb[q] = log2(sum_k 2^(Q.K)) via tf32 mma.
// Block: 128 compact-q rows x all 2048 keys (K tiles of 128). dyn smem 69632 B.
// ---------------------------------------------------------------------------
__global__ __launch_bounds__(256) void k_lsum() {
    extern __shared__ __align__(16) uint32_t smu[];
    uint32_t* Qs = smu;              // [128][PAD]
    uint32_t* Ks = smu + 128*PAD;    // [128][PAD]

    int qt = blockIdx.x, bh = blockIdx.y;
    int b = bh >> 4;
    int cnt = g_cnt[b];
    if (qt * 128 >= cnt) return;
    int tid = threadIdx.x;
    int w = tid >> 5, lane = tid & 31;
    int g = lane >> 2, t = lane & 3;
    const float* Qbase = g_Qh + (size_t)bh * SS * 64;
    const float* Kbase = g_Kh + (size_t)bh * SS * 64;

    // stage gathered Q tile
#pragma unroll
    for (int i = 0; i < 8; i++) {
        int idx = tid + 256 * i;
        int row = idx >> 4, d4 = idx & 15;
        int ci = qt*128 + row;
        float4 v = make_float4(0.f, 0.f, 0.f, 0.f);
        if (ci < cnt) {
            int s = g_qidx[b*SS + ci];
            v = *(const float4*)(Qbase + ((size_t)s << 6) + d4 * 4);
        }
        uint4 u; u.x = f2tf(v.x); u.y = f2tf(v.y); u.z = f2tf(v.z); u.w = f2tf(v.w);
        *(uint4*)(Qs + row*PAD + d4*4) = u;
    }
    __syncthreads();
    uint32_t A[8][4];
#pragma unroll
    for (int kc = 0; kc < 8; kc++) {
        int r0 = (w*16 + g)*PAD + t + 8*kc;
        A[kc][0] = Qs[r0];
        A[kc][1] = Qs[r0 + 8*PAD];
        A[kc][2] = Qs[r0 + 4];
        A[kc][3] = Qs[r0 + 8*PAD + 4];
    }
    float rs_lo = 0.f, rs_hi = 0.f;
    for (int kt = 0; kt < 16; kt++) {
        __syncthreads();
#pragma unroll
        for (int i = 0; i < 8; i++) {
            int idx = tid + 256 * i;
            int row = idx >> 4, d4 = idx & 15;
            float4 v = *(const float4*)(Kbase + ((size_t)(kt*128 + row) << 6) + d4 * 4);
            uint4 u; u.x = f2tf(v.x); u.y = f2tf(v.y); u.z = f2tf(v.z); u.w = f2tf(v.w);
            *(uint4*)(Ks + row*PAD + d4*4) = u;
        }
        __syncthreads();
#pragma unroll 4
        for (int nc = 0; nc < 16; nc++) {
            float c[4] = {0.f, 0.f, 0.f, 0.f};
            int nb = (nc*8 + g)*PAD + t;
#pragma unroll
            for (int kc = 0; kc < 8; kc++)
                mma8(c, A[kc], Ks[nb + 8*kc], Ks[nb + 8*kc + 4]);
            rs_lo += exp2f(c[0]) + exp2f(c[1]);
            rs_hi += exp2f(c[2]) + exp2f(c[3]);
        }
    }
    rs_lo += __shfl_xor_sync(0xffffffffu, rs_lo, 1);
    rs_lo += __shfl_xor_sync(0xffffffffu, rs_lo, 2);
    rs_hi += __shfl_xor_sync(0xffffffffu, rs_hi, 1);
    rs_hi += __shfl_xor_sync(0xffffffffu, rs_hi, 2);
    if (t == 0) {
        int ci = qt*128 + w*16 + g;
        if (ci < cnt)     g_lb[bh*SS + ci]     = log2f(rs_lo);
        if (ci + 8 < cnt) g_lb[bh*SS + ci + 8] = log2f(rs_hi);
    }
}

// ---------------------------------------------------------------------------
// Kernel 3 (pass B): w[k] = sum_q 2^(Q.K - lb[q]) via tf32 mma.
// Block: 256-key tile x all compact q (tiles of 128). dyn smem 113152 B.
// ---------------------------------------------------------------------------
__global__ __launch_bounds__(256) void k_wsum() {
    extern __shared__ __align__(16) uint32_t smu[];
    uint32_t* Ks = smu;                       // [256][PAD]
    uint32_t* Qs = smu + 256*PAD;             // [128][PAD]
    float* lbs = (float*)(smu + 256*PAD + 128*PAD);  // [128]
    float* wp  = lbs + 128;                   // [8][256] per-warp private

    int kt = blockIdx.x, bh = blockIdx.y;
    int b = bh >> 4;
    int cnt = g_cnt[b];
    int tid = threadIdx.x;
    int w = tid >> 5, lane = tid & 31;
    int g = lane >> 2, t = lane & 3;
    const float* Qbase = g_Qh + (size_t)bh * SS * 64;
    const float* Kbase = g_Kh + (size_t)bh * SS * 64;

#pragma unroll
    for (int i = 0; i < 8; i++) wp[tid + 256*i] = 0.f;

    // stage 256-key K tile (persistent)
#pragma unroll
    for (int i = 0; i < 16; i++) {
        int idx = tid + 256 * i;
        int row = idx >> 4, d4 = idx & 15;
        float4 v = *(const float4*)(Kbase + ((size_t)(kt*256 + row) << 6) + d4 * 4);
        uint4 u; u.x = f2tf(v.x); u.y = f2tf(v.y); u.z = f2tf(v.z); u.w = f2tf(v.w);
        *(uint4*)(Ks + row*PAD + d4*4) = u;
    }

    int nqt = (cnt + 127) >> 7;
    for (int qt = 0; qt < nqt; qt++) {
        __syncthreads();
#pragma unroll
        for (int i = 0; i < 8; i++) {
            int idx = tid + 256 * i;
            int row = idx >> 4, d4 = idx & 15;
            int ci = qt*128 + row;
            float4 v = make_float4(0.f, 0.f, 0.f, 0.f);
            if (ci < cnt) {
                int s = g_qidx[b*SS + ci];
                v = *(const float4*)(Qbase + ((size_t)s << 6) + d4 * 4);
            }
            uint4 u; u.x = f2tf(v.x); u.y = f2tf(v.y); u.z = f2tf(v.z); u.w = f2tf(v.w);
            *(uint4*)(Qs + row*PAD + d4*4) = u;
        }
        if (tid < 128) {
            int ci = qt*128 + tid;
            lbs[tid] = (ci < cnt) ? g_lb[bh*SS + ci] : 1e9f;
        }
        __syncthreads();
        uint32_t A[8][4];
#pragma unroll
        for (int kc = 0; kc < 8; kc++) {
            int r0 = (w*16 + g)*PAD + t + 8*kc;
            A[kc][0] = Qs[r0];
            A[kc][1] = Qs[r0 + 8*PAD];
            A[kc][2] = Qs[r0 + 4];
            A[kc][3] = Qs[r0 + 8*PAD + 4];
        }
        float lb_lo = lbs[w*16 + g], lb_hi = lbs[w*16 + g + 8];
#pragma unroll 4
        for (int nc = 0; nc < 32; nc++) {
            float c[4] = {0.f, 0.f, 0.f, 0.f};
            int nb = (nc*8 + g)*PAD + t;
#pragma unroll
            for (int kc = 0; kc < 8; kc++)
                mma8(c, A[kc], Ks[nb + 8*kc], Ks[nb + 8*kc + 4]);
            float p0 = exp2f(c[0] - lb_lo) + exp2f(c[2] - lb_hi);
            float p1 = exp2f(c[1] - lb_lo) + exp2f(c[3] - lb_hi);
            p0 += __shfl_xor_sync(0xffffffffu, p0, 4);
            p0 += __shfl_xor_sync(0xffffffffu, p0, 8);
            p0 += __shfl_xor_sync(0xffffffffu, p0, 16);
            p1 += __shfl_xor_sync(0xffffffffu, p1, 4);
            p1 += __shfl_xor_sync(0xffffffffu, p1, 8);
            p1 += __shfl_xor_sync(0xffffffffu, p1, 16);
            if (g == 0) {
                wp[w*256 + nc*8 + 2*t]     += p0;
                wp[w*256 + nc*8 + 2*t + 1] += p1;
            }
        }
    }
    __syncthreads();
    float wv = 0.f;
#pragma unroll
    for (int i = 0; i < 8; i++) wv += wp[i*256 + tid];
    g_w[bh*SS + kt*256 + tid] = wv;
}

// ---------------------------------------------------------------------------
// Kernel 4: y[b,h,j] = sum_k w[b,h,k] * v[b,k,j]
// ---------------------------------------------------------------------------
__global__ __launch_bounds__(256) void k_ypart(const float* __restrict__ v) {
    int id = blockIdx.x;
    int kt = id & 15;
    int jt = (id >> 4) & 3;
    int b  = id >> 6;
    __shared__ float wsh[16][128];
    int tid = threadIdx.x;
#pragma unroll
    for (int i = 0; i < 8; i++) {
        int idx = tid + 256 * i;
        int h = idx >> 7, kk = idx & 127;
        wsh[h][kk] = g_w[(b*HH + h) * SS + kt*128 + kk];
    }
    __syncthreads();
    int j = jt * 256 + tid;
    float acc[16];
#pragma unroll
    for (int h = 0; h < 16; h++) acc[h] = 0.f;
    const float* vb = v + ((size_t)b * SS + kt*128) * 1024 + j;
    for (int kk = 0; kk < 128; kk++) {
        float vv = vb[(size_t)kk * 1024];
#pragma unroll
        for (int h = 0; h < 16; h++) acc[h] += wsh[h][kk] * vv;
    }
#pragma unroll
    for (int h = 0; h < 16; h++)
        g_ypart[((size_t)(kt*BB + b) * HH + h) * DD + j] = acc[h];
}

__global__ void k_yred() {
    int i = blockIdx.x * 256 + threadIdx.x;
    float s = 0.f;
#pragma unroll
    for (int kt = 0; kt < 16; kt++) s += g_ypart[(size_t)kt * (BB*HH*DD) + i];
    g_y[i] = s;
}

// ---------------------------------------------------------------------------
// Kernel 5: cs[b,c] = sum_j y[b,h(c),j]*Wv[j,c] + cnt_b*bv[c]  (split-j)
// ---------------------------------------------------------------------------
__global__ void k_cs_part(const float* __restrict__ Wv) {
    int bid = blockIdx.x;
    int b = bid >> 5, jc = bid & 31;
    int tid = threadIdx.x;
    int c0 = tid * 4;
    int h = c0 >> 6;
    const float* yrow = g_y + (size_t)(b*HH + h) * DD;
    float4 s = make_float4(0.f, 0.f, 0.f, 0.f);
#pragma unroll 8
    for (int j = jc*32; j < jc*32 + 32; j++) {
        float yv = yrow[j];
        float4 w4 = *(const float4*)(Wv + (size_t)j * 1024 + c0);
        s.x += yv * w4.x; s.y += yv * w4.y; s.z += yv * w4.z; s.w += yv * w4.w;
    }
    *(float4*)(g_csp + (size_t)bid * DD + c0) = s;
}

__global__ void k_cs_red(const float* __restrict__ bv) {
    int idx = blockIdx.x * 256 + threadIdx.x;
    int b = idx >> 10, c = idx & 1023;
    float s = 0.f;
#pragma unroll
    for (int jc = 0; jc < 32; jc++) s += g_csp[(size_t)(b*32 + jc) * DD + c];
    g_cs[idx] = s + g_cntf[b] * bv[c];
}

// ---------------------------------------------------------------------------
// Kernel 6: out[b,d] = sum_c cs[b,c]*Wo[c,d] + cnt_b*bo[d]   (split-c)
// ---------------------------------------------------------------------------
__global__ void k_out_part(const float* __restrict__ Wo) {
    int bid = blockIdx.x;
    int b = bid >> 5, jc = bid & 31;
    int tid = threadIdx.x;
    int d0 = tid * 4;
    const float* cs = g_cs + (size_t)b * 1024;
    float4 s = make_float4(0.f, 0.f, 0.f, 0.f);
#pragma unroll 8
    for (int c = jc*32; c < jc*32 + 32; c++) {
        float cv = cs[c];
        float4 w4 = *(const float4*)(Wo + (size_t)c * 1024 + d0);
        s.x += cv * w4.x; s.y += cv * w4.y; s.z += cv * w4.z; s.w += cv * w4.w;
    }
    *(float4*)(g_outp + (size_t)bid * DD + d0) = s;
}

__global__ void k_out_red(const float* __restrict__ bo, float* __restrict__ out) {
    int idx = blockIdx.x * 256 + threadIdx.x;
    int b = idx >> 10, d = idx & 1023;
    float s = 0.f;
#pragma unroll
    for (int jc = 0; jc < 32; jc++) s += g_outp[(size_t)(b*32 + jc) * DD + d];
    out[idx] = s + g_cntf[b] * bo[d];
}

// ---------------------------------------------------------------------------
extern "C" void kernel_launch(void* const* d_in, const int* in_sizes, int n_in,
                              void* d_out, int out_size) {
    const float* q    = (const float*)d_in[0];
    const float* k    = (const float*)d_in[1];
    const float* v    = (const float*)d_in[2];
    const int*   mask = (const int*)  d_in[3];
    const float* Wq   = (const float*)d_in[4];
    const float* bq   = (const float*)d_in[5];
    const float* Wk   = (const float*)d_in[6];
    const float* bk   = (const float*)d_in[7];
    const float* Wv   = (const float*)d_in[8];
    const float* bv   = (const float*)d_in[9];
    const float* Wo   = (const float*)d_in[10];
    const float* bo   = (const float*)d_in[11];
    float* out = (float*)d_out;

    const int SM_PROJ = 2 * 128 * PAD * 4;                      // 69632
    const int SM_LSUM = 2 * 128 * PAD * 4;                      // 69632
    const int SM_WSUM = (256 + 128) * PAD * 4 + 512 + 8192;     // 113152

    cudaFuncSetAttribute(k_proj, cudaFuncAttributeMaxDynamicSharedMemorySize, SM_PROJ);
    cudaFuncSetAttribute(k_lsum, cudaFuncAttributeMaxDynamicSharedMemorySize, SM_LSUM);
    cudaFuncSetAttribute(k_wsum, cudaFuncAttributeMaxDynamicSharedMemorySize, SM_WSUM);

    k_compact<<<BB, 256>>>(mask);
    k_proj<<<dim3(32, 8), 256, SM_PROJ>>>(q, Wq, bq, QSCALE, 0);
    k_proj<<<dim3(32, 8), 256, SM_PROJ>>>(k, Wk, bk, 1.0f, 1);
    k_lsum<<<dim3(16, 32), 256, SM_LSUM>>>();
    k_wsum<<<dim3(8, 32), 256, SM_WSUM>>>();
    k_ypart<<<128, 256>>>(v);
    k_yred<<<128, 256>>>();
    k_cs_part<<<64, 256>>>(Wv);
    k_cs_red<<<8, 256>>>(bv);
    k_out_part<<<64, 256>>>(Wo);
    k_out_red<<<8, 256>>>(bo, out);
}